// round 3
// baseline (speedup 1.0000x reference)
#include <cuda_runtime.h>

// ---------------------------------------------------------------------------
// Fused MHA forward: x@Wq/Wk/Wv -> flash attention -> @Wo
// B=2, S=2048, D=1024, H=16, Hd=64, fp32.
// Round 0: fp32 SIMT baseline. 64x64 tiled GEMMs (4x4/thread), flash attn
// with online softmax. Structure chosen so tensor-core swap is incremental.
// ---------------------------------------------------------------------------

#define D_MODEL 1024
#define NHEADS  16
#define HD      64
#define BATCH   2
#define SEQ     2048
#define MTOT    (BATCH * SEQ)   // 4096

// Scratch (allocation-free rule: __device__ globals)
__device__ float g_q[BATCH * NHEADS * SEQ * HD];   // [b,h,s,d]
__device__ float g_k[BATCH * NHEADS * SEQ * HD];
__device__ float g_v[BATCH * NHEADS * SEQ * HD];
__device__ float g_att[MTOT * D_MODEL];            // [b,s, h*HD+d]

// ---------------------------------------------------------------------------
// QKV projection GEMM: C = x @ W + b, written in split-head layout.
// Tile: 64(M) x 64(N) x 16(K), 256 threads, 4x4 accum per thread.
// SMEM A stored transposed [k][m] so both operands are LDS.128 in the loop.
// grid.z in {0,1,2} selects Q/K/V.
// ---------------------------------------------------------------------------
__global__ __launch_bounds__(256) void qkv_gemm(
    const float* __restrict__ x,
    const float* __restrict__ Wq, const float* __restrict__ bq,
    const float* __restrict__ Wk, const float* __restrict__ bk,
    const float* __restrict__ Wv, const float* __restrict__ bv)
{
    const float* W;
    const float* bias;
    float* outp;
    if (blockIdx.z == 0)      { W = Wq; bias = bq; outp = g_q; }
    else if (blockIdx.z == 1) { W = Wk; bias = bk; outp = g_k; }
    else                      { W = Wv; bias = bv; outp = g_v; }

    __shared__ float As[16][64];   // [k][m]
    __shared__ float Ws[16][64];   // [k][n]

    const int tid = threadIdx.x;
    const int tx = tid & 15, ty = tid >> 4;
    const int bm = blockIdx.y * 64;
    const int bn = blockIdx.x * 64;

    const int arow = tid >> 2, aquad = tid & 3;    // A loader: 64 rows x 4 quads
    const int wrow = tid >> 4, wquad = tid & 15;   // W loader: 16 rows x 16 quads

    float acc[4][4] = {};

    for (int k0 = 0; k0 < D_MODEL; k0 += 16) {
        // Issue global loads before the sync so latency overlaps prior compute
        float4 av = *reinterpret_cast<const float4*>(x + (bm + arow) * D_MODEL + k0 + aquad * 4);
        float4 wv = *reinterpret_cast<const float4*>(W + (k0 + wrow) * D_MODEL + bn + wquad * 4);
        __syncthreads();
        As[aquad * 4 + 0][arow] = av.x;
        As[aquad * 4 + 1][arow] = av.y;
        As[aquad * 4 + 2][arow] = av.z;
        As[aquad * 4 + 3][arow] = av.w;
        *reinterpret_cast<float4*>(&Ws[wrow][wquad * 4]) = wv;
        __syncthreads();

#pragma unroll
        for (int k = 0; k < 16; ++k) {
            float4 a = *reinterpret_cast<const float4*>(&As[k][ty * 4]);
            float4 w = *reinterpret_cast<const float4*>(&Ws[k][tx * 4]);
            acc[0][0] += a.x * w.x; acc[0][1] += a.x * w.y; acc[0][2] += a.x * w.z; acc[0][3] += a.x * w.w;
            acc[1][0] += a.y * w.x; acc[1][1] += a.y * w.y; acc[1][2] += a.y * w.z; acc[1][3] += a.y * w.w;
            acc[2][0] += a.z * w.x; acc[2][1] += a.z * w.y; acc[2][2] += a.z * w.z; acc[2][3] += a.z * w.w;
            acc[3][0] += a.w * w.x; acc[3][1] += a.w * w.y; acc[3][2] += a.w * w.z; acc[3][3] += a.w * w.w;
        }
    }

    // N-tile == HD == 64, so head index == blockIdx.x
    const int h = blockIdx.x;
    const float4 bb = *reinterpret_cast<const float4*>(bias + bn + tx * 4);
#pragma unroll
    for (int i = 0; i < 4; ++i) {
        int m = bm + ty * 4 + i;
        int b_ = m >> 11;            // / SEQ
        int s_ = m & (SEQ - 1);
        float4 r;
        r.x = acc[i][0] + bb.x;
        r.y = acc[i][1] + bb.y;
        r.z = acc[i][2] + bb.z;
        r.w = acc[i][3] + bb.w;
        *reinterpret_cast<float4*>(outp + ((size_t)((b_ * NHEADS + h) * SEQ + s_)) * HD + tx * 4) = r;
    }
}

// ---------------------------------------------------------------------------
// Flash attention: one block = (b,h) x 64 query rows, loops over 32 key tiles.
// Q/K stored d-transposed in SMEM -> score loop is 2x LDS.128 + 16 FMA per d.
// Online softmax state (m, l) per row, in registers.
// ---------------------------------------------------------------------------
#define ATTN_SMEM ((3 * 64 * 64 + 64 * 65) * 4)

__global__ __launch_bounds__(256) void attn_kernel()
{
    extern __shared__ float sm[];
    float* Qt = sm;                 // [d][r]  64x64
    float* Kt = sm + 64 * 64;       // [d][c]  64x64
    float* Vs = sm + 2 * 64 * 64;   // [c][d]  64x64
    float* Pt = sm + 3 * 64 * 64;   // [c][r]  64x65 (pad: 2-way conflicts max)

    const int tid = threadIdx.x;
    const int tx = tid & 15, ty = tid >> 4;
    const int bh = blockIdx.y;                 // b*H + h
    const int q0 = blockIdx.x * 64;

    const float* Qg = g_q + ((size_t)bh * SEQ + q0) * HD;
    const float* Kg = g_k + (size_t)bh * SEQ * HD;
    const float* Vg = g_v + (size_t)bh * SEQ * HD;

    const float scale = 0.125f;   // 1/sqrt(64), folded into Q at load

    // Load Q tile transposed (and pre-scaled)
    for (int i = tid; i < 64 * 16; i += 256) {
        int r = i >> 4, quad = i & 15;
        float4 v = *reinterpret_cast<const float4*>(Qg + r * HD + quad * 4);
        Qt[(quad * 4 + 0) * 64 + r] = v.x * scale;
        Qt[(quad * 4 + 1) * 64 + r] = v.y * scale;
        Qt[(quad * 4 + 2) * 64 + r] = v.z * scale;
        Qt[(quad * 4 + 3) * 64 + r] = v.w * scale;
    }

    float o[4][4] = {};
    float mrow[4] = {-1e30f, -1e30f, -1e30f, -1e30f};
    float lrow[4] = {0.f, 0.f, 0.f, 0.f};

    for (int kt = 0; kt < SEQ / 64; ++kt) {
        const float* Kgt = Kg + kt * 64 * HD;
        const float* Vgt = Vg + kt * 64 * HD;

        __syncthreads();   // previous PV done with Vs/Pt, scores done with Kt
        for (int i = tid; i < 64 * 16; i += 256) {
            int r = i >> 4, quad = i & 15;
            float4 v = *reinterpret_cast<const float4*>(Kgt + r * HD + quad * 4);
            Kt[(quad * 4 + 0) * 64 + r] = v.x;
            Kt[(quad * 4 + 1) * 64 + r] = v.y;
            Kt[(quad * 4 + 2) * 64 + r] = v.z;
            Kt[(quad * 4 + 3) * 64 + r] = v.w;
            float4 vv = *reinterpret_cast<const float4*>(Vgt + r * HD + quad * 4);
            *reinterpret_cast<float4*>(&Vs[r * 64 + quad * 4]) = vv;
        }
        __syncthreads();

        // Scores: s[i][j] = sum_d Qt[d][4ty+i] * Kt[d][4tx+j]
        float s4[4][4] = {};
#pragma unroll 16
        for (int d = 0; d < 64; ++d) {
            float4 qv = *reinterpret_cast<const float4*>(&Qt[d * 64 + ty * 4]);
            float4 kv = *reinterpret_cast<const float4*>(&Kt[d * 64 + tx * 4]);
            s4[0][0] += qv.x * kv.x; s4[0][1] += qv.x * kv.y; s4[0][2] += qv.x * kv.z; s4[0][3] += qv.x * kv.w;
            s4[1][0] += qv.y * kv.x; s4[1][1] += qv.y * kv.y; s4[1][2] += qv.y * kv.z; s4[1][3] += qv.y * kv.w;
            s4[2][0] += qv.z * kv.x; s4[2][1] += qv.z * kv.y; s4[2][2] += qv.z * kv.z; s4[2][3] += qv.z * kv.w;
            s4[3][0] += qv.w * kv.x; s4[3][1] += qv.w * kv.y; s4[3][2] += qv.w * kv.z; s4[3][3] += qv.w * kv.w;
        }

        // Online softmax per row; xor-shuffle over the 16 tx lanes
#pragma unroll
        for (int i = 0; i < 4; ++i) {
            float mx = fmaxf(fmaxf(s4[i][0], s4[i][1]), fmaxf(s4[i][2], s4[i][3]));
#pragma unroll
            for (int off = 1; off <= 8; off <<= 1)
                mx = fmaxf(mx, __shfl_xor_sync(0xffffffffu, mx, off, 32));
            float mnew = fmaxf(mrow[i], mx);
            float alpha = __expf(mrow[i] - mnew);
            mrow[i] = mnew;
            float rs = 0.f;
#pragma unroll
            for (int j = 0; j < 4; ++j) {
                s4[i][j] = __expf(s4[i][j] - mnew);
                rs += s4[i][j];
            }
#pragma unroll
            for (int off = 1; off <= 8; off <<= 1)
                rs += __shfl_xor_sync(0xffffffffu, rs, off, 32);
            lrow[i] = lrow[i] * alpha + rs;
#pragma unroll
            for (int j = 0; j < 4; ++j) o[i][j] *= alpha;
            // Store P transposed: Pt[c][r]
#pragma unroll
            for (int j = 0; j < 4; ++j)
                Pt[(tx * 4 + j) * 65 + ty * 4 + i] = s4[i][j];
        }
        __syncthreads();

        // PV: o[i][j] += sum_c Pt[c][4ty+i] * Vs[c][4tx+j]
#pragma unroll 16
        for (int c = 0; c < 64; ++c) {
            float p0 = Pt[c * 65 + ty * 4 + 0];
            float p1 = Pt[c * 65 + ty * 4 + 1];
            float p2 = Pt[c * 65 + ty * 4 + 2];
            float p3 = Pt[c * 65 + ty * 4 + 3];
            float4 vv = *reinterpret_cast<const float4*>(&Vs[c * 64 + tx * 4]);
            o[0][0] += p0 * vv.x; o[0][1] += p0 * vv.y; o[0][2] += p0 * vv.z; o[0][3] += p0 * vv.w;
            o[1][0] += p1 * vv.x; o[1][1] += p1 * vv.y; o[1][2] += p1 * vv.z; o[1][3] += p1 * vv.w;
            o[2][0] += p2 * vv.x; o[2][1] += p2 * vv.y; o[2][2] += p2 * vv.z; o[2][3] += p2 * vv.w;
            o[3][0] += p3 * vv.x; o[3][1] += p3 * vv.y; o[3][2] += p3 * vv.z; o[3][3] += p3 * vv.w;
        }
    }

    // Epilogue: normalize and write attended in [b, s, h*HD+d] layout
    const int b_ = bh >> 4;
    const int h  = bh & 15;
#pragma unroll
    for (int i = 0; i < 4; ++i) {
        float inv = 1.0f / lrow[i];
        int q = q0 + ty * 4 + i;
        float4 r;
        r.x = o[i][0] * inv;
        r.y = o[i][1] * inv;
        r.z = o[i][2] * inv;
        r.w = o[i][3] * inv;
        *reinterpret_cast<float4*>(&g_att[((size_t)(b_ * SEQ + q)) * D_MODEL + h * HD + tx * 4]) = r;
    }
}

// ---------------------------------------------------------------------------
// Output projection: out = g_att @ Wo + bo   (row-major [4096,1024])
// ---------------------------------------------------------------------------
__global__ __launch_bounds__(256) void out_gemm(
    const float* __restrict__ Wo, const float* __restrict__ bo,
    float* __restrict__ out)
{
    __shared__ float As[16][64];
    __shared__ float Ws[16][64];

    const int tid = threadIdx.x;
    const int tx = tid & 15, ty = tid >> 4;
    const int bm = blockIdx.y * 64;
    const int bn = blockIdx.x * 64;

    const int arow = tid >> 2, aquad = tid & 3;
    const int wrow = tid >> 4, wquad = tid & 15;

    float acc[4][4] = {};

    for (int k0 = 0; k0 < D_MODEL; k0 += 16) {
        float4 av = *reinterpret_cast<const float4*>(g_att + ((size_t)(bm + arow)) * D_MODEL + k0 + aquad * 4);
        float4 wv = *reinterpret_cast<const float4*>(Wo + (k0 + wrow) * D_MODEL + bn + wquad * 4);
        __syncthreads();
        As[aquad * 4 + 0][arow] = av.x;
        As[aquad * 4 + 1][arow] = av.y;
        As[aquad * 4 + 2][arow] = av.z;
        As[aquad * 4 + 3][arow] = av.w;
        *reinterpret_cast<float4*>(&Ws[wrow][wquad * 4]) = wv;
        __syncthreads();

#pragma unroll
        for (int k = 0; k < 16; ++k) {
            float4 a = *reinterpret_cast<const float4*>(&As[k][ty * 4]);
            float4 w = *reinterpret_cast<const float4*>(&Ws[k][tx * 4]);
            acc[0][0] += a.x * w.x; acc[0][1] += a.x * w.y; acc[0][2] += a.x * w.z; acc[0][3] += a.x * w.w;
            acc[1][0] += a.y * w.x; acc[1][1] += a.y * w.y; acc[1][2] += a.y * w.z; acc[1][3] += a.y * w.w;
            acc[2][0] += a.z * w.x; acc[2][1] += a.z * w.y; acc[2][2] += a.z * w.z; acc[2][3] += a.z * w.w;
            acc[3][0] += a.w * w.x; acc[3][1] += a.w * w.y; acc[3][2] += a.w * w.z; acc[3][3] += a.w * w.w;
        }
    }

    const float4 bb = *reinterpret_cast<const float4*>(bo + bn + tx * 4);
#pragma unroll
    for (int i = 0; i < 4; ++i) {
        int m = bm + ty * 4 + i;
        float4 r;
        r.x = acc[i][0] + bb.x;
        r.y = acc[i][1] + bb.y;
        r.z = acc[i][2] + bb.z;
        r.w = acc[i][3] + bb.w;
        *reinterpret_cast<float4*>(out + (size_t)m * D_MODEL + bn + tx * 4) = r;
    }
}

// ---------------------------------------------------------------------------
extern "C" void kernel_launch(void* const* d_in, const int* in_sizes, int n_in,
                              void* d_out, int out_size)
{
    const float* x  = (const float*)d_in[0];
    const float* Wq = (const float*)d_in[1];
    const float* bq = (const float*)d_in[2];
    const float* Wk = (const float*)d_in[3];
    const float* bk = (const float*)d_in[4];
    const float* Wv = (const float*)d_in[5];
    const float* bv = (const float*)d_in[6];
    const float* Wo = (const float*)d_in[7];
    const float* bo = (const float*)d_in[8];
    float* out = (float*)d_out;

    // 1) QKV projections (fused over grid.z)
    dim3 g1(D_MODEL / 64, MTOT / 64, 3);   // 16 x 64 x 3
    qkv_gemm<<<g1, 256>>>(x, Wq, bq, Wk, bk, Wv, bv);

    // 2) Flash attention
    cudaFuncSetAttribute(attn_kernel, cudaFuncAttributeMaxDynamicSharedMemorySize, ATTN_SMEM);
    dim3 g2(SEQ / 64, BATCH * NHEADS);     // 32 x 32
    attn_kernel<<<g2, 256, ATTN_SMEM>>>();

    // 3) Output projection
    dim3 g3(D_MODEL / 64, MTOT / 64);      // 16 x 64
    out_gemm<<<g3, 256>>>(Wo, bo, out);
}

// round 4
// speedup vs baseline: 1.2930x; 1.2930x over previous
#include <cuda_runtime.h>
#include <math.h>

// ---------------------------------------------------------------------------
// Fused MHA forward on tf32 tensor cores (mma.sync.m16n8k8) with 3xTF32
// error compensation. B=2, S=2048, D=1024, H=16, Hd=64, fp32 in/out.
//   - QKV proj / QK^T / out-proj: full hi/lo split (3 mma)  -> ~fp32 accuracy
//   - PV: V split only (2 mma), P single-rounded            -> ~3e-4 rel err
// Swizzled SMEM (c ^= 4*(r&7)) makes all mma fragment LDS conflict-free.
// ---------------------------------------------------------------------------

#define D_MODEL 1024
#define NHEADS  16
#define HD      64
#define BATCH   2
#define SEQ     2048
#define MTOT    (BATCH * SEQ)   // 4096

__device__ float g_q[BATCH * NHEADS * SEQ * HD];
__device__ float g_k[BATCH * NHEADS * SEQ * HD];
__device__ float g_v[BATCH * NHEADS * SEQ * HD];
__device__ float g_att[MTOT * D_MODEL];

__device__ __forceinline__ unsigned f2tf(float x) {
    unsigned r; asm("cvt.rna.tf32.f32 %0, %1;" : "=r"(r) : "f"(x)); return r;
}
__device__ __forceinline__ void split_tf32(float x, unsigned& hi, unsigned& lo) {
    hi = f2tf(x);
    lo = f2tf(x - __uint_as_float(hi));
}
__device__ __forceinline__ void mma_tf32(float* d, const unsigned* a, const unsigned* b) {
    asm volatile(
        "mma.sync.aligned.m16n8k8.row.col.f32.tf32.tf32.f32 "
        "{%0,%1,%2,%3}, {%4,%5,%6,%7}, {%8,%9}, {%0,%1,%2,%3};\n"
        : "+f"(d[0]), "+f"(d[1]), "+f"(d[2]), "+f"(d[3])
        : "r"(a[0]), "r"(a[1]), "r"(a[2]), "r"(a[3]), "r"(b[0]), "r"(b[1]));
}

// XOR swizzle: element (r,c) stored at column c ^ (4*(r&7)). Any fragment
// access pattern (8 rows x 4 aligned cols) hits 32 distinct banks.
#define SW32(r, c) (((r) << 5) + ((c) ^ (((r) & 7) << 2)))
#define SW64(r, c) (((r) << 6) + ((c) ^ (((r) & 7) << 2)))

// ---------------------------------------------------------------------------
// QKV projection: CTA tile 128(M) x 64(N), K-step 32, 8 warps, warp 32x32.
// A = x [m][k] row-major -> smem direct. B = W [k][n] -> transposed into
// smem [n][k] at load (conflict-free STS by lane mapping).
// ---------------------------------------------------------------------------
__global__ __launch_bounds__(256, 2) void qkv_gemm(
    const float* __restrict__ x,
    const float* __restrict__ Wq, const float* __restrict__ bq,
    const float* __restrict__ Wk, const float* __restrict__ bk,
    const float* __restrict__ Wv, const float* __restrict__ bv)
{
    const float* W; const float* bias; float* outp;
    if (blockIdx.z == 0)      { W = Wq; bias = bq; outp = g_q; }
    else if (blockIdx.z == 1) { W = Wk; bias = bk; outp = g_k; }
    else                      { W = Wv; bias = bv; outp = g_v; }

    __shared__ float As[128 * 32];
    __shared__ float Bs[64 * 32];

    const int tid  = threadIdx.x;
    const int warp = tid >> 5, lane = tid & 31;
    const int g = lane >> 2, tig = lane & 3;
    const int wm = (warp >> 1) * 32, wn = (warp & 1) * 32;
    const int bm = blockIdx.y * 128, bn = blockIdx.x * 64;

    // loaders
    const int am  = tid >> 1;             // A row 0..127
    const int ak4 = (tid & 1) * 16;       // A float4 col base (4 float4s)
    const int bkk = tid >> 3;             // B k row 0..31
    const int bn0 = tid & 7;              // B n base (+8j)

    float acc[2][4][4] = {};

    for (int k0 = 0; k0 < D_MODEL; k0 += 32) {
        float4 av[4];
#pragma unroll
        for (int q = 0; q < 4; ++q)
            av[q] = *reinterpret_cast<const float4*>(x + (size_t)(bm + am) * D_MODEL + k0 + ak4 + q * 4);
        float bv8[8];
#pragma unroll
        for (int j = 0; j < 8; ++j)
            bv8[j] = W[(size_t)(k0 + bkk) * D_MODEL + bn + bn0 + 8 * j];

        __syncthreads();
#pragma unroll
        for (int q = 0; q < 4; ++q)
            *reinterpret_cast<float4*>(&As[SW32(am, ak4 + q * 4)]) = av[q];
#pragma unroll
        for (int j = 0; j < 8; ++j)
            Bs[SW32(bn0 + 8 * j, bkk)] = bv8[j];
        __syncthreads();

#pragma unroll
        for (int kk = 0; kk < 32; kk += 8) {
            unsigned ahi[2][4], alo[2][4];
#pragma unroll
            for (int t = 0; t < 2; ++t) {
                int r0 = wm + t * 16 + g;
                split_tf32(As[SW32(r0,     kk + tig)],     ahi[t][0], alo[t][0]);
                split_tf32(As[SW32(r0 + 8, kk + tig)],     ahi[t][1], alo[t][1]);
                split_tf32(As[SW32(r0,     kk + tig + 4)], ahi[t][2], alo[t][2]);
                split_tf32(As[SW32(r0 + 8, kk + tig + 4)], ahi[t][3], alo[t][3]);
            }
            unsigned bhi[4][2], blo[4][2];
#pragma unroll
            for (int u = 0; u < 4; ++u) {
                int n = wn + u * 8 + g;
                split_tf32(Bs[SW32(n, kk + tig)],     bhi[u][0], blo[u][0]);
                split_tf32(Bs[SW32(n, kk + tig + 4)], bhi[u][1], blo[u][1]);
            }
#pragma unroll
            for (int t = 0; t < 2; ++t)
#pragma unroll
                for (int u = 0; u < 4; ++u) {
                    mma_tf32(acc[t][u], ahi[t], bhi[u]);
                    mma_tf32(acc[t][u], alo[t], bhi[u]);
                    mma_tf32(acc[t][u], ahi[t], blo[u]);
                }
        }
    }

    // Epilogue: N-tile == 64 == HD, head = blockIdx.x. Write split-head layout.
    const int h = blockIdx.x;
#pragma unroll
    for (int t = 0; t < 2; ++t)
#pragma unroll
        for (int u = 0; u < 4; ++u) {
            int dcol = wn + u * 8 + 2 * tig;
            float bx = bias[bn + dcol], by = bias[bn + dcol + 1];
            int m0 = bm + wm + t * 16 + g;
#pragma unroll
            for (int half = 0; half < 2; ++half) {
                int m = m0 + half * 8;
                int b_ = m >> 11, s_ = m & (SEQ - 1);
                float2 r;
                r.x = acc[t][u][half * 2 + 0] + bx;
                r.y = acc[t][u][half * 2 + 1] + by;
                *reinterpret_cast<float2*>(
                    outp + ((size_t)((b_ * NHEADS + h) * SEQ + s_)) * HD + dcol) = r;
            }
        }
}

// ---------------------------------------------------------------------------
// Flash attention, tf32 mma. CTA = 64 q-rows x (b,h). 4 warps, 16 q-rows each.
// QK^T: full split (3 mma). PV: V split only (2 mma), P single tf32.
// ---------------------------------------------------------------------------
#define ATTN_SMEM (4 * 64 * 64 * 4)   // Qs, Ks, Vt, Ps = 64KB

__global__ __launch_bounds__(128, 3) void attn_kernel()
{
    extern __shared__ float sm[];
    float* Qs = sm;                 // [q][d]  swizzled
    float* Ks = sm + 4096;          // [c][d]  (= B col-major for QK^T)
    float* Vt = sm + 8192;          // [d][c]  (= B col-major for PV)
    float* Ps = sm + 12288;         // [q][c]

    const int tid  = threadIdx.x;
    const int warp = tid >> 5, lane = tid & 31;
    const int g = lane >> 2, tig = lane & 3;
    const int qw = warp * 16;
    const int bh = blockIdx.y;
    const int q0 = blockIdx.x * 64;

    const float* Qg = g_q + ((size_t)bh * SEQ + q0) * HD;
    const float* Kg = g_k + (size_t)bh * SEQ * HD;
    const float* Vg = g_v + (size_t)bh * SEQ * HD;
    const float scale = 0.125f;

    // Load Q once (scale folded), swizzled
#pragma unroll
    for (int it = 0; it < 8; ++it) {
        int idx = it * 128 + tid;
        int r = idx >> 4, c4 = (idx & 15) * 4;
        float4 v = *reinterpret_cast<const float4*>(Qg + r * HD + c4);
        v.x *= scale; v.y *= scale; v.z *= scale; v.w *= scale;
        *reinterpret_cast<float4*>(&Qs[SW64(r, c4)]) = v;
    }

    float o[8][4] = {};
    float mrow[2] = {-1e30f, -1e30f};
    float lrow[2] = {0.f, 0.f};

    for (int kt = 0; kt < SEQ / 64; ++kt) {
        const float* Kgt = Kg + kt * 64 * HD;
        const float* Vgt = Vg + kt * 64 * HD;

        __syncthreads();   // prev PV done with Vt/Ps; prev QK done with Ks
#pragma unroll
        for (int it = 0; it < 8; ++it) {
            int idx = it * 128 + tid;
            int r = idx >> 4, c4 = (idx & 15) * 4;
            float4 kv = *reinterpret_cast<const float4*>(Kgt + r * HD + c4);
            *reinterpret_cast<float4*>(&Ks[SW64(r, c4)]) = kv;
            float4 vv = *reinterpret_cast<const float4*>(Vgt + r * HD + c4);
            Vt[SW64(c4 + 0, r)] = vv.x;   // transpose for PV B operand
            Vt[SW64(c4 + 1, r)] = vv.y;
            Vt[SW64(c4 + 2, r)] = vv.z;
            Vt[SW64(c4 + 3, r)] = vv.w;
        }
        __syncthreads();

        // ---- scores: S = Q @ K^T (split 3x) ----
        float s[8][4] = {};
#pragma unroll
        for (int kk = 0; kk < 64; kk += 8) {
            unsigned ahi[4], alo[4];
            split_tf32(Qs[SW64(qw + g,     kk + tig)],     ahi[0], alo[0]);
            split_tf32(Qs[SW64(qw + g + 8, kk + tig)],     ahi[1], alo[1]);
            split_tf32(Qs[SW64(qw + g,     kk + tig + 4)], ahi[2], alo[2]);
            split_tf32(Qs[SW64(qw + g + 8, kk + tig + 4)], ahi[3], alo[3]);
#pragma unroll
            for (int u = 0; u < 8; ++u) {
                unsigned bhi[2], blo[2];
                split_tf32(Ks[SW64(u * 8 + g, kk + tig)],     bhi[0], blo[0]);
                split_tf32(Ks[SW64(u * 8 + g, kk + tig + 4)], bhi[1], blo[1]);
                mma_tf32(s[u], ahi, bhi);
                mma_tf32(s[u], alo, bhi);
                mma_tf32(s[u], ahi, blo);
            }
        }

        // ---- online softmax (rows qw+g and qw+g+8; cols over tig quad) ----
        float mx0 = -1e30f, mx1 = -1e30f;
#pragma unroll
        for (int u = 0; u < 8; ++u) {
            mx0 = fmaxf(mx0, fmaxf(s[u][0], s[u][1]));
            mx1 = fmaxf(mx1, fmaxf(s[u][2], s[u][3]));
        }
        mx0 = fmaxf(mx0, __shfl_xor_sync(0xffffffffu, mx0, 1));
        mx0 = fmaxf(mx0, __shfl_xor_sync(0xffffffffu, mx0, 2));
        mx1 = fmaxf(mx1, __shfl_xor_sync(0xffffffffu, mx1, 1));
        mx1 = fmaxf(mx1, __shfl_xor_sync(0xffffffffu, mx1, 2));

        float m0n = fmaxf(mrow[0], mx0), m1n = fmaxf(mrow[1], mx1);
        float a0 = __expf(mrow[0] - m0n), a1 = __expf(mrow[1] - m1n);
        mrow[0] = m0n; mrow[1] = m1n;

        float rs0 = 0.f, rs1 = 0.f;
#pragma unroll
        for (int u = 0; u < 8; ++u) {
            s[u][0] = __expf(s[u][0] - m0n); rs0 += s[u][0];
            s[u][1] = __expf(s[u][1] - m0n); rs0 += s[u][1];
            s[u][2] = __expf(s[u][2] - m1n); rs1 += s[u][2];
            s[u][3] = __expf(s[u][3] - m1n); rs1 += s[u][3];
        }
        rs0 += __shfl_xor_sync(0xffffffffu, rs0, 1);
        rs0 += __shfl_xor_sync(0xffffffffu, rs0, 2);
        rs1 += __shfl_xor_sync(0xffffffffu, rs1, 1);
        rs1 += __shfl_xor_sync(0xffffffffu, rs1, 2);
        lrow[0] = lrow[0] * a0 + rs0;
        lrow[1] = lrow[1] * a1 + rs1;

#pragma unroll
        for (int u = 0; u < 8; ++u) {
            o[u][0] *= a0; o[u][1] *= a0; o[u][2] *= a1; o[u][3] *= a1;
            // store P (warp-private rows) for the PV A-fragment
            *reinterpret_cast<float2*>(&Ps[SW64(qw + g,     u * 8 + 2 * tig)]) =
                make_float2(s[u][0], s[u][1]);
            *reinterpret_cast<float2*>(&Ps[SW64(qw + g + 8, u * 8 + 2 * tig)]) =
                make_float2(s[u][2], s[u][3]);
        }
        __syncwarp();   // P rows are written & read by this warp only

        // ---- PV: O += P @ V (P single tf32, V split 2x) ----
#pragma unroll
        for (int kk = 0; kk < 64; kk += 8) {
            unsigned pa[4];
            pa[0] = f2tf(Ps[SW64(qw + g,     kk + tig)]);
            pa[1] = f2tf(Ps[SW64(qw + g + 8, kk + tig)]);
            pa[2] = f2tf(Ps[SW64(qw + g,     kk + tig + 4)]);
            pa[3] = f2tf(Ps[SW64(qw + g + 8, kk + tig + 4)]);
#pragma unroll
            for (int u = 0; u < 8; ++u) {
                unsigned bhi[2], blo[2];
                split_tf32(Vt[SW64(u * 8 + g, kk + tig)],     bhi[0], blo[0]);
                split_tf32(Vt[SW64(u * 8 + g, kk + tig + 4)], bhi[1], blo[1]);
                mma_tf32(o[u], pa, bhi);
                mma_tf32(o[u], pa, blo);
            }
        }
    }

    // Epilogue: normalize and write [b, s, h*HD + d]
    const int b_ = bh >> 4, h = bh & 15;
    const float inv0 = 1.0f / lrow[0], inv1 = 1.0f / lrow[1];
    const int r0 = q0 + qw + g, r1 = r0 + 8;
#pragma unroll
    for (int u = 0; u < 8; ++u) {
        int d = u * 8 + 2 * tig;
        *reinterpret_cast<float2*>(
            &g_att[((size_t)(b_ * SEQ + r0)) * D_MODEL + h * HD + d]) =
            make_float2(o[u][0] * inv0, o[u][1] * inv0);
        *reinterpret_cast<float2*>(
            &g_att[((size_t)(b_ * SEQ + r1)) * D_MODEL + h * HD + d]) =
            make_float2(o[u][2] * inv1, o[u][3] * inv1);
    }
}

// ---------------------------------------------------------------------------
// Output projection: out = g_att @ Wo + bo (same tiling as qkv_gemm)
// ---------------------------------------------------------------------------
__global__ __launch_bounds__(256, 2) void out_gemm(
    const float* __restrict__ Wo, const float* __restrict__ bo,
    float* __restrict__ out)
{
    __shared__ float As[128 * 32];
    __shared__ float Bs[64 * 32];

    const int tid  = threadIdx.x;
    const int warp = tid >> 5, lane = tid & 31;
    const int g = lane >> 2, tig = lane & 3;
    const int wm = (warp >> 1) * 32, wn = (warp & 1) * 32;
    const int bm = blockIdx.y * 128, bn = blockIdx.x * 64;

    const int am  = tid >> 1;
    const int ak4 = (tid & 1) * 16;
    const int bkk = tid >> 3;
    const int bn0 = tid & 7;

    float acc[2][4][4] = {};

    for (int k0 = 0; k0 < D_MODEL; k0 += 32) {
        float4 av[4];
#pragma unroll
        for (int q = 0; q < 4; ++q)
            av[q] = *reinterpret_cast<const float4*>(g_att + (size_t)(bm + am) * D_MODEL + k0 + ak4 + q * 4);
        float bv8[8];
#pragma unroll
        for (int j = 0; j < 8; ++j)
            bv8[j] = Wo[(size_t)(k0 + bkk) * D_MODEL + bn + bn0 + 8 * j];

        __syncthreads();
#pragma unroll
        for (int q = 0; q < 4; ++q)
            *reinterpret_cast<float4*>(&As[SW32(am, ak4 + q * 4)]) = av[q];
#pragma unroll
        for (int j = 0; j < 8; ++j)
            Bs[SW32(bn0 + 8 * j, bkk)] = bv8[j];
        __syncthreads();

#pragma unroll
        for (int kk = 0; kk < 32; kk += 8) {
            unsigned ahi[2][4], alo[2][4];
#pragma unroll
            for (int t = 0; t < 2; ++t) {
                int r0 = wm + t * 16 + g;
                split_tf32(As[SW32(r0,     kk + tig)],     ahi[t][0], alo[t][0]);
                split_tf32(As[SW32(r0 + 8, kk + tig)],     ahi[t][1], alo[t][1]);
                split_tf32(As[SW32(r0,     kk + tig + 4)], ahi[t][2], alo[t][2]);
                split_tf32(As[SW32(r0 + 8, kk + tig + 4)], ahi[t][3], alo[t][3]);
            }
            unsigned bhi[4][2], blo[4][2];
#pragma unroll
            for (int u = 0; u < 4; ++u) {
                int n = wn + u * 8 + g;
                split_tf32(Bs[SW32(n, kk + tig)],     bhi[u][0], blo[u][0]);
                split_tf32(Bs[SW32(n, kk + tig + 4)], bhi[u][1], blo[u][1]);
            }
#pragma unroll
            for (int t = 0; t < 2; ++t)
#pragma unroll
                for (int u = 0; u < 4; ++u) {
                    mma_tf32(acc[t][u], ahi[t], bhi[u]);
                    mma_tf32(acc[t][u], alo[t], bhi[u]);
                    mma_tf32(acc[t][u], ahi[t], blo[u]);
                }
        }
    }

#pragma unroll
    for (int t = 0; t < 2; ++t)
#pragma unroll
        for (int u = 0; u < 4; ++u) {
            int dcol = wn + u * 8 + 2 * tig;
            float bx = bo[bn + dcol], by = bo[bn + dcol + 1];
            int m0 = bm + wm + t * 16 + g;
#pragma unroll
            for (int half = 0; half < 2; ++half) {
                int m = m0 + half * 8;
                float2 r;
                r.x = acc[t][u][half * 2 + 0] + bx;
                r.y = acc[t][u][half * 2 + 1] + by;
                *reinterpret_cast<float2*>(out + (size_t)m * D_MODEL + bn + dcol) = r;
            }
        }
}

// ---------------------------------------------------------------------------
extern "C" void kernel_launch(void* const* d_in, const int* in_sizes, int n_in,
                              void* d_out, int out_size)
{
    const float* x  = (const float*)d_in[0];
    const float* Wq = (const float*)d_in[1];
    const float* bq = (const float*)d_in[2];
    const float* Wk = (const float*)d_in[3];
    const float* bk = (const float*)d_in[4];
    const float* Wv = (const float*)d_in[5];
    const float* bv = (const float*)d_in[6];
    const float* Wo = (const float*)d_in[7];
    const float* bo = (const float*)d_in[8];
    float* out = (float*)d_out;

    dim3 g1(D_MODEL / 64, MTOT / 128, 3);   // 16 x 32 x 3
    qkv_gemm<<<g1, 256>>>(x, Wq, bq, Wk, bk, Wv, bv);

    cudaFuncSetAttribute(attn_kernel, cudaFuncAttributeMaxDynamicSharedMemorySize, ATTN_SMEM);
    dim3 g2(SEQ / 64, BATCH * NHEADS);      // 32 x 32
    attn_kernel<<<g2, 128, ATTN_SMEM>>>();

    dim3 g3(D_MODEL / 64, MTOT / 128);      // 16 x 32
    out_gemm<<<g3, 256>>>(Wo, bo, out);
}

// round 5
// speedup vs baseline: 1.2932x; 1.0002x over previous
#include <cuda_runtime.h>
#include <math.h>

// ---------------------------------------------------------------------------
// Fused MHA forward on tf32 tensor cores (mma.sync.m16n8k8) with 3xTF32
// error compensation. B=2, S=2048, D=1024, H=16, Hd=64, fp32 in/out.
//   - QKV proj / QK^T / out-proj: full hi/lo split (3 mma)  -> ~fp32 accuracy
//   - PV: V split only (2 mma), P single-rounded            -> ~3e-4 rel err
// Swizzled SMEM (c ^= 4*(r&7)) makes all mma fragment LDS conflict-free.
// ---------------------------------------------------------------------------

#define D_MODEL 1024
#define NHEADS  16
#define HD      64
#define BATCH   2
#define SEQ     2048
#define MTOT    (BATCH * SEQ)   // 4096

__device__ float g_q[BATCH * NHEADS * SEQ * HD];
__device__ float g_k[BATCH * NHEADS * SEQ * HD];
__device__ float g_v[BATCH * NHEADS * SEQ * HD];
__device__ float g_att[MTOT * D_MODEL];

__device__ __forceinline__ unsigned f2tf(float x) {
    unsigned r; asm("cvt.rna.tf32.f32 %0, %1;" : "=r"(r) : "f"(x)); return r;
}
__device__ __forceinline__ void split_tf32(float x, unsigned& hi, unsigned& lo) {
    hi = f2tf(x);
    lo = f2tf(x - __uint_as_float(hi));
}
__device__ __forceinline__ void mma_tf32(float* d, const unsigned* a, const unsigned* b) {
    asm volatile(
        "mma.sync.aligned.m16n8k8.row.col.f32.tf32.tf32.f32 "
        "{%0,%1,%2,%3}, {%4,%5,%6,%7}, {%8,%9}, {%0,%1,%2,%3};\n"
        : "+f"(d[0]), "+f"(d[1]), "+f"(d[2]), "+f"(d[3])
        : "r"(a[0]), "r"(a[1]), "r"(a[2]), "r"(a[3]), "r"(b[0]), "r"(b[1]));
}

// XOR swizzle: element (r,c) stored at column c ^ (4*(r&7)). Any fragment
// access pattern (8 rows x 4 aligned cols) hits 32 distinct banks.
#define SW32(r, c) (((r) << 5) + ((c) ^ (((r) & 7) << 2)))
#define SW64(r, c) (((r) << 6) + ((c) ^ (((r) & 7) << 2)))

// ---------------------------------------------------------------------------
// QKV projection: CTA tile 128(M) x 64(N), K-step 32, 8 warps, warp 32x32.
// A = x [m][k] row-major -> smem direct. B = W [k][n] -> transposed into
// smem [n][k] at load (conflict-free STS by lane mapping).
// ---------------------------------------------------------------------------
__global__ __launch_bounds__(256, 2) void qkv_gemm(
    const float* __restrict__ x,
    const float* __restrict__ Wq, const float* __restrict__ bq,
    const float* __restrict__ Wk, const float* __restrict__ bk,
    const float* __restrict__ Wv, const float* __restrict__ bv)
{
    const float* W; const float* bias; float* outp;
    if (blockIdx.z == 0)      { W = Wq; bias = bq; outp = g_q; }
    else if (blockIdx.z == 1) { W = Wk; bias = bk; outp = g_k; }
    else                      { W = Wv; bias = bv; outp = g_v; }

    __shared__ float As[128 * 32];
    __shared__ float Bs[64 * 32];

    const int tid  = threadIdx.x;
    const int warp = tid >> 5, lane = tid & 31;
    const int g = lane >> 2, tig = lane & 3;
    const int wm = (warp >> 1) * 32, wn = (warp & 1) * 32;
    const int bm = blockIdx.y * 128, bn = blockIdx.x * 64;

    // loaders
    const int am  = tid >> 1;             // A row 0..127
    const int ak4 = (tid & 1) * 16;       // A float4 col base (4 float4s)
    const int bkk = tid >> 3;             // B k row 0..31
    const int bn0 = tid & 7;              // B n base (+8j)

    float acc[2][4][4] = {};

    for (int k0 = 0; k0 < D_MODEL; k0 += 32) {
        float4 av[4];
#pragma unroll
        for (int q = 0; q < 4; ++q)
            av[q] = *reinterpret_cast<const float4*>(x + (size_t)(bm + am) * D_MODEL + k0 + ak4 + q * 4);
        float bv8[8];
#pragma unroll
        for (int j = 0; j < 8; ++j)
            bv8[j] = W[(size_t)(k0 + bkk) * D_MODEL + bn + bn0 + 8 * j];

        __syncthreads();
#pragma unroll
        for (int q = 0; q < 4; ++q)
            *reinterpret_cast<float4*>(&As[SW32(am, ak4 + q * 4)]) = av[q];
#pragma unroll
        for (int j = 0; j < 8; ++j)
            Bs[SW32(bn0 + 8 * j, bkk)] = bv8[j];
        __syncthreads();

#pragma unroll
        for (int kk = 0; kk < 32; kk += 8) {
            unsigned ahi[2][4], alo[2][4];
#pragma unroll
            for (int t = 0; t < 2; ++t) {
                int r0 = wm + t * 16 + g;
                split_tf32(As[SW32(r0,     kk + tig)],     ahi[t][0], alo[t][0]);
                split_tf32(As[SW32(r0 + 8, kk + tig)],     ahi[t][1], alo[t][1]);
                split_tf32(As[SW32(r0,     kk + tig + 4)], ahi[t][2], alo[t][2]);
                split_tf32(As[SW32(r0 + 8, kk + tig + 4)], ahi[t][3], alo[t][3]);
            }
            unsigned bhi[4][2], blo[4][2];
#pragma unroll
            for (int u = 0; u < 4; ++u) {
                int n = wn + u * 8 + g;
                split_tf32(Bs[SW32(n, kk + tig)],     bhi[u][0], blo[u][0]);
                split_tf32(Bs[SW32(n, kk + tig + 4)], bhi[u][1], blo[u][1]);
            }
#pragma unroll
            for (int t = 0; t < 2; ++t)
#pragma unroll
                for (int u = 0; u < 4; ++u) {
                    mma_tf32(acc[t][u], ahi[t], bhi[u]);
                    mma_tf32(acc[t][u], alo[t], bhi[u]);
                    mma_tf32(acc[t][u], ahi[t], blo[u]);
                }
        }
    }

    // Epilogue: N-tile == 64 == HD, head = blockIdx.x. Write split-head layout.
    const int h = blockIdx.x;
#pragma unroll
    for (int t = 0; t < 2; ++t)
#pragma unroll
        for (int u = 0; u < 4; ++u) {
            int dcol = wn + u * 8 + 2 * tig;
            float bx = bias[bn + dcol], by = bias[bn + dcol + 1];
            int m0 = bm + wm + t * 16 + g;
#pragma unroll
            for (int half = 0; half < 2; ++half) {
                int m = m0 + half * 8;
                int b_ = m >> 11, s_ = m & (SEQ - 1);
                float2 r;
                r.x = acc[t][u][half * 2 + 0] + bx;
                r.y = acc[t][u][half * 2 + 1] + by;
                *reinterpret_cast<float2*>(
                    outp + ((size_t)((b_ * NHEADS + h) * SEQ + s_)) * HD + dcol) = r;
            }
        }
}

// ---------------------------------------------------------------------------
// Flash attention, tf32 mma. CTA = 64 q-rows x (b,h). 4 warps, 16 q-rows each.
// QK^T: full split (3 mma). PV: V split only (2 mma), P single tf32.
// ---------------------------------------------------------------------------
#define ATTN_SMEM (4 * 64 * 64 * 4)   // Qs, Ks, Vt, Ps = 64KB

__global__ __launch_bounds__(128, 3) void attn_kernel()
{
    extern __shared__ float sm[];
    float* Qs = sm;                 // [q][d]  swizzled
    float* Ks = sm + 4096;          // [c][d]  (= B col-major for QK^T)
    float* Vt = sm + 8192;          // [d][c]  (= B col-major for PV)
    float* Ps = sm + 12288;         // [q][c]

    const int tid  = threadIdx.x;
    const int warp = tid >> 5, lane = tid & 31;
    const int g = lane >> 2, tig = lane & 3;
    const int qw = warp * 16;
    const int bh = blockIdx.y;
    const int q0 = blockIdx.x * 64;

    const float* Qg = g_q + ((size_t)bh * SEQ + q0) * HD;
    const float* Kg = g_k + (size_t)bh * SEQ * HD;
    const float* Vg = g_v + (size_t)bh * SEQ * HD;
    const float scale = 0.125f;

    // Load Q once (scale folded), swizzled
#pragma unroll
    for (int it = 0; it < 8; ++it) {
        int idx = it * 128 + tid;
        int r = idx >> 4, c4 = (idx & 15) * 4;
        float4 v = *reinterpret_cast<const float4*>(Qg + r * HD + c4);
        v.x *= scale; v.y *= scale; v.z *= scale; v.w *= scale;
        *reinterpret_cast<float4*>(&Qs[SW64(r, c4)]) = v;
    }

    float o[8][4] = {};
    float mrow[2] = {-1e30f, -1e30f};
    float lrow[2] = {0.f, 0.f};

    for (int kt = 0; kt < SEQ / 64; ++kt) {
        const float* Kgt = Kg + kt * 64 * HD;
        const float* Vgt = Vg + kt * 64 * HD;

        __syncthreads();   // prev PV done with Vt/Ps; prev QK done with Ks
#pragma unroll
        for (int it = 0; it < 8; ++it) {
            int idx = it * 128 + tid;
            int r = idx >> 4, c4 = (idx & 15) * 4;
            float4 kv = *reinterpret_cast<const float4*>(Kgt + r * HD + c4);
            *reinterpret_cast<float4*>(&Ks[SW64(r, c4)]) = kv;
            float4 vv = *reinterpret_cast<const float4*>(Vgt + r * HD + c4);
            Vt[SW64(c4 + 0, r)] = vv.x;   // transpose for PV B operand
            Vt[SW64(c4 + 1, r)] = vv.y;
            Vt[SW64(c4 + 2, r)] = vv.z;
            Vt[SW64(c4 + 3, r)] = vv.w;
        }
        __syncthreads();

        // ---- scores: S = Q @ K^T (split 3x) ----
        float s[8][4] = {};
#pragma unroll
        for (int kk = 0; kk < 64; kk += 8) {
            unsigned ahi[4], alo[4];
            split_tf32(Qs[SW64(qw + g,     kk + tig)],     ahi[0], alo[0]);
            split_tf32(Qs[SW64(qw + g + 8, kk + tig)],     ahi[1], alo[1]);
            split_tf32(Qs[SW64(qw + g,     kk + tig + 4)], ahi[2], alo[2]);
            split_tf32(Qs[SW64(qw + g + 8, kk + tig + 4)], ahi[3], alo[3]);
#pragma unroll
            for (int u = 0; u < 8; ++u) {
                unsigned bhi[2], blo[2];
                split_tf32(Ks[SW64(u * 8 + g, kk + tig)],     bhi[0], blo[0]);
                split_tf32(Ks[SW64(u * 8 + g, kk + tig + 4)], bhi[1], blo[1]);
                mma_tf32(s[u], ahi, bhi);
                mma_tf32(s[u], alo, bhi);
                mma_tf32(s[u], ahi, blo);
            }
        }

        // ---- online softmax (rows qw+g and qw+g+8; cols over tig quad) ----
        float mx0 = -1e30f, mx1 = -1e30f;
#pragma unroll
        for (int u = 0; u < 8; ++u) {
            mx0 = fmaxf(mx0, fmaxf(s[u][0], s[u][1]));
            mx1 = fmaxf(mx1, fmaxf(s[u][2], s[u][3]));
        }
        mx0 = fmaxf(mx0, __shfl_xor_sync(0xffffffffu, mx0, 1));
        mx0 = fmaxf(mx0, __shfl_xor_sync(0xffffffffu, mx0, 2));
        mx1 = fmaxf(mx1, __shfl_xor_sync(0xffffffffu, mx1, 1));
        mx1 = fmaxf(mx1, __shfl_xor_sync(0xffffffffu, mx1, 2));

        float m0n = fmaxf(mrow[0], mx0), m1n = fmaxf(mrow[1], mx1);
        float a0 = __expf(mrow[0] - m0n), a1 = __expf(mrow[1] - m1n);
        mrow[0] = m0n; mrow[1] = m1n;

        float rs0 = 0.f, rs1 = 0.f;
#pragma unroll
        for (int u = 0; u < 8; ++u) {
            s[u][0] = __expf(s[u][0] - m0n); rs0 += s[u][0];
            s[u][1] = __expf(s[u][1] - m0n); rs0 += s[u][1];
            s[u][2] = __expf(s[u][2] - m1n); rs1 += s[u][2];
            s[u][3] = __expf(s[u][3] - m1n); rs1 += s[u][3];
        }
        rs0 += __shfl_xor_sync(0xffffffffu, rs0, 1);
        rs0 += __shfl_xor_sync(0xffffffffu, rs0, 2);
        rs1 += __shfl_xor_sync(0xffffffffu, rs1, 1);
        rs1 += __shfl_xor_sync(0xffffffffu, rs1, 2);
        lrow[0] = lrow[0] * a0 + rs0;
        lrow[1] = lrow[1] * a1 + rs1;

#pragma unroll
        for (int u = 0; u < 8; ++u) {
            o[u][0] *= a0; o[u][1] *= a0; o[u][2] *= a1; o[u][3] *= a1;
            // store P (warp-private rows) for the PV A-fragment
            *reinterpret_cast<float2*>(&Ps[SW64(qw + g,     u * 8 + 2 * tig)]) =
                make_float2(s[u][0], s[u][1]);
            *reinterpret_cast<float2*>(&Ps[SW64(qw + g + 8, u * 8 + 2 * tig)]) =
                make_float2(s[u][2], s[u][3]);
        }
        __syncwarp();   // P rows are written & read by this warp only

        // ---- PV: O += P @ V (P single tf32, V split 2x) ----
#pragma unroll
        for (int kk = 0; kk < 64; kk += 8) {
            unsigned pa[4];
            pa[0] = f2tf(Ps[SW64(qw + g,     kk + tig)]);
            pa[1] = f2tf(Ps[SW64(qw + g + 8, kk + tig)]);
            pa[2] = f2tf(Ps[SW64(qw + g,     kk + tig + 4)]);
            pa[3] = f2tf(Ps[SW64(qw + g + 8, kk + tig + 4)]);
#pragma unroll
            for (int u = 0; u < 8; ++u) {
                unsigned bhi[2], blo[2];
                split_tf32(Vt[SW64(u * 8 + g, kk + tig)],     bhi[0], blo[0]);
                split_tf32(Vt[SW64(u * 8 + g, kk + tig + 4)], bhi[1], blo[1]);
                mma_tf32(o[u], pa, bhi);
                mma_tf32(o[u], pa, blo);
            }
        }
    }

    // Epilogue: normalize and write [b, s, h*HD + d]
    const int b_ = bh >> 4, h = bh & 15;
    const float inv0 = 1.0f / lrow[0], inv1 = 1.0f / lrow[1];
    const int r0 = q0 + qw + g, r1 = r0 + 8;
#pragma unroll
    for (int u = 0; u < 8; ++u) {
        int d = u * 8 + 2 * tig;
        *reinterpret_cast<float2*>(
            &g_att[((size_t)(b_ * SEQ + r0)) * D_MODEL + h * HD + d]) =
            make_float2(o[u][0] * inv0, o[u][1] * inv0);
        *reinterpret_cast<float2*>(
            &g_att[((size_t)(b_ * SEQ + r1)) * D_MODEL + h * HD + d]) =
            make_float2(o[u][2] * inv1, o[u][3] * inv1);
    }
}

// ---------------------------------------------------------------------------
// Output projection: out = g_att @ Wo + bo (same tiling as qkv_gemm)
// ---------------------------------------------------------------------------
__global__ __launch_bounds__(256, 2) void out_gemm(
    const float* __restrict__ Wo, const float* __restrict__ bo,
    float* __restrict__ out)
{
    __shared__ float As[128 * 32];
    __shared__ float Bs[64 * 32];

    const int tid  = threadIdx.x;
    const int warp = tid >> 5, lane = tid & 31;
    const int g = lane >> 2, tig = lane & 3;
    const int wm = (warp >> 1) * 32, wn = (warp & 1) * 32;
    const int bm = blockIdx.y * 128, bn = blockIdx.x * 64;

    const int am  = tid >> 1;
    const int ak4 = (tid & 1) * 16;
    const int bkk = tid >> 3;
    const int bn0 = tid & 7;

    float acc[2][4][4] = {};

    for (int k0 = 0; k0 < D_MODEL; k0 += 32) {
        float4 av[4];
#pragma unroll
        for (int q = 0; q < 4; ++q)
            av[q] = *reinterpret_cast<const float4*>(g_att + (size_t)(bm + am) * D_MODEL + k0 + ak4 + q * 4);
        float bv8[8];
#pragma unroll
        for (int j = 0; j < 8; ++j)
            bv8[j] = Wo[(size_t)(k0 + bkk) * D_MODEL + bn + bn0 + 8 * j];

        __syncthreads();
#pragma unroll
        for (int q = 0; q < 4; ++q)
            *reinterpret_cast<float4*>(&As[SW32(am, ak4 + q * 4)]) = av[q];
#pragma unroll
        for (int j = 0; j < 8; ++j)
            Bs[SW32(bn0 + 8 * j, bkk)] = bv8[j];
        __syncthreads();

#pragma unroll
        for (int kk = 0; kk < 32; kk += 8) {
            unsigned ahi[2][4], alo[2][4];
#pragma unroll
            for (int t = 0; t < 2; ++t) {
                int r0 = wm + t * 16 + g;
                split_tf32(As[SW32(r0,     kk + tig)],     ahi[t][0], alo[t][0]);
                split_tf32(As[SW32(r0 + 8, kk + tig)],     ahi[t][1], alo[t][1]);
                split_tf32(As[SW32(r0,     kk + tig + 4)], ahi[t][2], alo[t][2]);
                split_tf32(As[SW32(r0 + 8, kk + tig + 4)], ahi[t][3], alo[t][3]);
            }
            unsigned bhi[4][2], blo[4][2];
#pragma unroll
            for (int u = 0; u < 4; ++u) {
                int n = wn + u * 8 + g;
                split_tf32(Bs[SW32(n, kk + tig)],     bhi[u][0], blo[u][0]);
                split_tf32(Bs[SW32(n, kk + tig + 4)], bhi[u][1], blo[u][1]);
            }
#pragma unroll
            for (int t = 0; t < 2; ++t)
#pragma unroll
                for (int u = 0; u < 4; ++u) {
                    mma_tf32(acc[t][u], ahi[t], bhi[u]);
                    mma_tf32(acc[t][u], alo[t], bhi[u]);
                    mma_tf32(acc[t][u], ahi[t], blo[u]);
                }
        }
    }

#pragma unroll
    for (int t = 0; t < 2; ++t)
#pragma unroll
        for (int u = 0; u < 4; ++u) {
            int dcol = wn + u * 8 + 2 * tig;
            float bx = bo[bn + dcol], by = bo[bn + dcol + 1];
            int m0 = bm + wm + t * 16 + g;
#pragma unroll
            for (int half = 0; half < 2; ++half) {
                int m = m0 + half * 8;
                float2 r;
                r.x = acc[t][u][half * 2 + 0] + bx;
                r.y = acc[t][u][half * 2 + 1] + by;
                *reinterpret_cast<float2*>(out + (size_t)m * D_MODEL + bn + dcol) = r;
            }
        }
}

// ---------------------------------------------------------------------------
extern "C" void kernel_launch(void* const* d_in, const int* in_sizes, int n_in,
                              void* d_out, int out_size)
{
    const float* x  = (const float*)d_in[0];
    const float* Wq = (const float*)d_in[1];
    const float* bq = (const float*)d_in[2];
    const float* Wk = (const float*)d_in[3];
    const float* bk = (const float*)d_in[4];
    const float* Wv = (const float*)d_in[5];
    const float* bv = (const float*)d_in[6];
    const float* Wo = (const float*)d_in[7];
    const float* bo = (const float*)d_in[8];
    float* out = (float*)d_out;

    dim3 g1(D_MODEL / 64, MTOT / 128, 3);   // 16 x 32 x 3
    qkv_gemm<<<g1, 256>>>(x, Wq, bq, Wk, bk, Wv, bv);

    cudaFuncSetAttribute(attn_kernel, cudaFuncAttributeMaxDynamicSharedMemorySize, ATTN_SMEM);
    dim3 g2(SEQ / 64, BATCH * NHEADS);      // 32 x 32
    attn_kernel<<<g2, 128, ATTN_SMEM>>>();

    dim3 g3(D_MODEL / 64, MTOT / 128);      // 16 x 32
    out_gemm<<<g3, 256>>>(Wo, bo, out);
}